// round 8
// baseline (speedup 1.0000x reference)
#include <cuda_runtime.h>

// TSK fuzzy system, single fused kernel.
// out[n] = sum_r fg_bar[n,r]*(x[n]·W[r]+b[r]);  separable normalization:
// fg_bar[n,r] = prod_m mgn[n,m,digit_m(r)], mgn = mg/sum_j mg.
// out[n] = x[n]·A[n]+c[n], A[n]=sum_r fg_bar W[r], c[n]=sum_r fg_bar b[r].
// f32x2 lanes pack a PAIR OF ADJACENT RULES (W stored once in smem).
// Each lane carries FOUR samples (lane, +32, +64, +96): every 16B W load
// feeds 8 FMA2. pm5/pm6 re-read from smem to stay under the 128-reg cliff.

#define NSAMP 1024
#define NGROUP 128   // grid.y: rule groups of 512
#define TILES 8      // grid.x: sample tiles of 128

typedef unsigned long long ull;

__device__ float g_part[NGROUP * 9 * NSAMP];  // [g][k][n]
__device__ int g_cnt[TILES];                  // zero-init; reset by finisher

__device__ __forceinline__ ull pack2(float f) {
    ull r; asm("mov.b64 %0, {%1, %1};" : "=l"(r) : "f"(f)); return r;
}
__device__ __forceinline__ ull pack2f(float a, float b) {
    ull r; asm("mov.b64 %0, {%1, %2};" : "=l"(r) : "f"(a), "f"(b)); return r;
}
__device__ __forceinline__ ull mul2(ull a, ull b) {
    ull d; asm("mul.rn.f32x2 %0, %1, %2;" : "=l"(d) : "l"(a), "l"(b)); return d;
}
__device__ __forceinline__ void fma2(ull& d, ull a, ull b) {
    asm("fma.rn.f32x2 %0, %1, %2, %0;" : "+l"(d) : "l"(a), "l"(b));
}
__device__ __forceinline__ void unpack2(ull v, float& lo, float& hi) {
    asm("mov.b64 {%0, %1}, %2;" : "=f"(lo), "=f"(hi) : "l"(v));
}

__global__ __launch_bounds__(128) void tsk_kernel(
    const float* __restrict__ x, const float* __restrict__ center,
    const float* __restrict__ sigma, const float* __restrict__ W,
    const float* __restrict__ b, float* __restrict__ out)
{
    // smW[p*8+k] = {W[2p][k], W[2p+1][k]}, p=0..255; smW[2048+p] = {b[2p],b[2p+1]}
    // After the main loop this whole region is reused as the reduction buffer
    // red[4][128][9] floats (2304 ull = 18,432 B, exact fit).
    __shared__ __align__(16) ull smW[2304];
    __shared__ float s_mg[128 * 33];             // memberships, padded rows
    __shared__ int isLast;

    int tid = threadIdx.x, lane = tid & 31, w = tid >> 5;
    int gy = blockIdx.y, tile = blockIdx.x;

    // ---- stage W (512 rules x 8) as adjacent-rule pairs ----
    const float4* Wg4 = reinterpret_cast<const float4*>(W + (size_t)gy * 4096);
#pragma unroll
    for (int i = tid; i < 512; i += 128) {
        int p = i >> 1, h = i & 1;               // pair p, k-half h
        float4 a = Wg4[(2 * p) * 2 + h];
        float4 c = Wg4[(2 * p + 1) * 2 + h];
        int base = p * 8 + h * 4;
        smW[base + 0] = pack2f(a.x, c.x);
        smW[base + 1] = pack2f(a.y, c.y);
        smW[base + 2] = pack2f(a.z, c.z);
        smW[base + 3] = pack2f(a.w, c.w);
    }
    {
        const float2* bg = reinterpret_cast<const float2*>(b + gy * 512);
        float2 v = bg[tid * 2], v2 = bg[tid * 2 + 1];
        smW[2048 + tid * 2] = pack2f(v.x, v.y);
        smW[2048 + tid * 2 + 1] = pack2f(v2.x, v2.y);
    }

    // ---- memberships: one thread per sample, 8 dims ----
    {
        int n = tile * 128 + tid;
        float* row = s_mg + tid * 33;
#pragma unroll
        for (int m = 0; m < 8; m++) {
            float xv = x[n * 8 + m];
            float e[4], sum = 0.f;
#pragma unroll
            for (int j = 0; j < 4; j++) {
                float d = xv - center[m * 4 + j];
                float sg = sigma[m * 4 + j];
                e[j] = __expf(-0.5f * d * d * sg * sg);
                sum += e[j];
            }
            float inv = 1.0f / sum;
#pragma unroll
            for (int j = 0; j < 4; j++) row[m * 4 + j] = e[j] * inv;
        }
    }
    __syncthreads();

    // ---- per-thread samples: lane, +32, +64, +96 ----
    const float* rs[4];
#pragma unroll
    for (int s = 0; s < 4; s++) rs[s] = s_mg + (lane + 32 * s) * 33;

    // warp's 128 rules: digits j0..j3 from chunk, j4 in {j4b, j4b+1}
    int chunk = gy * 2 + (w >> 1);
    int d0 = (chunk >> 6) & 3, d1 = (chunk >> 4) & 3, d2 = (chunk >> 2) & 3, d3 = chunk & 3;
    float pre[4];
    ull pm7p[4][2];
#pragma unroll
    for (int s = 0; s < 4; s++) {
        pre[s] = rs[s][d0] * rs[s][4 + d1] * rs[s][8 + d2] * rs[s][12 + d3];
        pm7p[s][0] = pack2f(rs[s][28], rs[s][29]);
        pm7p[s][1] = pack2f(rs[s][30], rs[s][31]);
    }
    int j4b = (w & 1) * 2;

    ull acc[4][9];
#pragma unroll
    for (int s = 0; s < 4; s++)
#pragma unroll
        for (int k = 0; k < 9; k++) acc[s][k] = 0ull;

    // ---- main loop: 128 rules/warp as 64 rule-pairs, 4 samples/lane ----
#pragma unroll 1
    for (int j4 = 0; j4 < 2; j4++) {
        float p4[4];
#pragma unroll
        for (int s = 0; s < 4; s++) p4[s] = pre[s] * rs[s][16 + j4b + j4];
#pragma unroll 1
        for (int j5 = 0; j5 < 4; j5++) {
            float p5[4];
#pragma unroll
            for (int s = 0; s < 4; s++) p5[s] = p4[s] * rs[s][20 + j5];
            int pb = w * 64 + j4 * 32 + j5 * 8;     // 8 rule-pairs here
            const ulonglong2* wp = reinterpret_cast<const ulonglong2*>(&smW[pb * 8]);
            const ulonglong2* bq = reinterpret_cast<const ulonglong2*>(&smW[2048 + pb]);
#pragma unroll
            for (int j6 = 0; j6 < 4; j6++) {
                ull f0[4], f1[4];
#pragma unroll
                for (int s = 0; s < 4; s++) {
                    ull p6 = pack2(p5[s] * rs[s][24 + j6]);
                    f0[s] = mul2(p6, pm7p[s][0]);
                    f1[s] = mul2(p6, pm7p[s][1]);
                }
                const ulonglong2* w0 = wp + j6 * 8;
                // pair 2*j6 (rules j7=0,1)
                {
                    ulonglong2 q = w0[0];
#pragma unroll
                    for (int s = 0; s < 4; s++) { fma2(acc[s][0], f0[s], q.x); fma2(acc[s][1], f0[s], q.y); }
                }
                {
                    ulonglong2 q = w0[1];
#pragma unroll
                    for (int s = 0; s < 4; s++) { fma2(acc[s][2], f0[s], q.x); fma2(acc[s][3], f0[s], q.y); }
                }
                {
                    ulonglong2 q = w0[2];
#pragma unroll
                    for (int s = 0; s < 4; s++) { fma2(acc[s][4], f0[s], q.x); fma2(acc[s][5], f0[s], q.y); }
                }
                {
                    ulonglong2 q = w0[3];
#pragma unroll
                    for (int s = 0; s < 4; s++) { fma2(acc[s][6], f0[s], q.x); fma2(acc[s][7], f0[s], q.y); }
                }
                // pair 2*j6+1 (rules j7=2,3)
                {
                    ulonglong2 q = w0[4];
#pragma unroll
                    for (int s = 0; s < 4; s++) { fma2(acc[s][0], f1[s], q.x); fma2(acc[s][1], f1[s], q.y); }
                }
                {
                    ulonglong2 q = w0[5];
#pragma unroll
                    for (int s = 0; s < 4; s++) { fma2(acc[s][2], f1[s], q.x); fma2(acc[s][3], f1[s], q.y); }
                }
                {
                    ulonglong2 q = w0[6];
#pragma unroll
                    for (int s = 0; s < 4; s++) { fma2(acc[s][4], f1[s], q.x); fma2(acc[s][5], f1[s], q.y); }
                }
                {
                    ulonglong2 q = w0[7];
#pragma unroll
                    for (int s = 0; s < 4; s++) { fma2(acc[s][6], f1[s], q.x); fma2(acc[s][7], f1[s], q.y); }
                }
                {
                    ulonglong2 bb = bq[j6];
#pragma unroll
                    for (int s = 0; s < 4; s++) { fma2(acc[s][8], f0[s], bb.x); fma2(acc[s][8], f1[s], bb.y); }
                }
            }
        }
    }

    // ---- collapse rule-pair lanes, cross-warp reduction (overlay W smem) ----
    __syncthreads();   // all warps done reading W
    float* red = reinterpret_cast<float*>(smW);  // [warp][sample128][9]
#pragma unroll
    for (int s = 0; s < 4; s++) {
#pragma unroll
        for (int k = 0; k < 9; k++) {
            float lo, hi;
            unpack2(acc[s][k], lo, hi);
            red[(w * 128 + lane + 32 * s) * 9 + k] = lo + hi;
        }
    }
    __syncthreads();

#pragma unroll 1
    for (int idx = tid; idx < 9 * 128; idx += 128) {
        int k = idx >> 7;
        int s = idx & 127;
        float a = red[(0 * 128 + s) * 9 + k] + red[(1 * 128 + s) * 9 + k]
                + red[(2 * 128 + s) * 9 + k] + red[(3 * 128 + s) * 9 + k];
        g_part[(gy * 9 + k) * NSAMP + tile * 128 + s] = a;
    }

    // ---- fused finalize: last CTA of this tile reduces over all groups ----
    __threadfence();
    __syncthreads();
    if (tid == 0) {
        int c = atomicAdd(&g_cnt[tile], 1);
        isLast = (c == NGROUP - 1) ? 1 : 0;
    }
    __syncthreads();
    if (isLast) {
        __threadfence();
        float* sA = s_mg;  // reuse: [s][k] 128*9
#pragma unroll 1
        for (int item = tid; item < 9 * 128; item += 128) {
            int k = item >> 7, s = item & 127;
            const float* p = g_part + k * NSAMP + tile * 128 + s;
            float a0 = 0.f, a1 = 0.f, a2 = 0.f, a3 = 0.f;
#pragma unroll 4
            for (int g = 0; g < NGROUP; g += 4) {
                a0 += p[(g + 0) * 9 * NSAMP];
                a1 += p[(g + 1) * 9 * NSAMP];
                a2 += p[(g + 2) * 9 * NSAMP];
                a3 += p[(g + 3) * 9 * NSAMP];
            }
            sA[s * 9 + k] = (a0 + a1) + (a2 + a3);
        }
        __syncthreads();
        {
            int n = tile * 128 + tid;
            float o = sA[tid * 9 + 8];
#pragma unroll
            for (int m = 0; m < 8; m++) o = fmaf(x[n * 8 + m], sA[tid * 9 + m], o);
            out[n] = o;
        }
        if (tid == 0) g_cnt[tile] = 0;  // reset for next graph replay
    }
}

extern "C" void kernel_launch(void* const* d_in, const int* in_sizes, int n_in,
                              void* d_out, int out_size) {
    const float* x      = (const float*)d_in[0];
    const float* center = (const float*)d_in[1];
    const float* sigma  = (const float*)d_in[2];
    const float* W      = (const float*)d_in[3];
    const float* b      = (const float*)d_in[4];
    float* out = (float*)d_out;

    dim3 grid(TILES, NGROUP);
    tsk_kernel<<<grid, 128>>>(x, center, sigma, W, b, out);
}

// round 10
// speedup vs baseline: 1.0379x; 1.0379x over previous
#include <cuda_runtime.h>
#include <cstdint>

// TSK fuzzy system via mma.sync tf32 tensor ops (baseline sm_80+ ISA).
// out[n] = sum_r fg_bar[n,r]*(x[n]·W[r]+b[r]); fg_bar separable-normalized:
// fg_bar[n,r] = prod_m mgn[n,m,digit_m(r)], mgn = mg/sum_j mg.
// Per CTA (tile of 128 samples, group of 512 rules):
//   D[128x16] = FG[128x512] @ Wb^T,  Wb[r] = [W[r][0..7], b[r], 0,...]
// FG fragments generated in registers (1 mul + 1 cvt per element via digit
// nesting); Wb^T staged in smem in m16n8k8.row.col B-fragment layout.

#define NSAMP 1024
#define NGROUP 128   // grid.y: rule groups of 512
#define TILES 8      // grid.x: sample tiles of 128

// dynamic smem: [0,32768) B fragments; [32768,+18432) union raw-Wb / mg / sA
#define SM_UNION_OFF 32768
#define SMEM_TOTAL (32768 + 18432)

__device__ float g_part[NGROUP * 9 * NSAMP];  // [g][k][n]
__device__ int g_cnt[TILES];                  // zero-init; reset by finisher

__device__ __forceinline__ uint32_t tf32r(float f) {
    uint32_t r; asm("cvt.rna.tf32.f32 %0, %1;" : "=r"(r) : "f"(f)); return r;
}
__device__ __forceinline__ void mma8(float* d, uint32_t a0, uint32_t a1,
                                     uint32_t a2, uint32_t a3,
                                     uint32_t b0, uint32_t b1) {
    asm volatile(
        "mma.sync.aligned.m16n8k8.row.col.f32.tf32.tf32.f32 "
        "{%0,%1,%2,%3}, {%4,%5,%6,%7}, {%8,%9}, {%0,%1,%2,%3};"
        : "+f"(d[0]), "+f"(d[1]), "+f"(d[2]), "+f"(d[3])
        : "r"(a0), "r"(a1), "r"(a2), "r"(a3), "r"(b0), "r"(b1));
}

__global__ __launch_bounds__(128) void tsk_kernel(
    const float* __restrict__ x, const float* __restrict__ center,
    const float* __restrict__ sigma, const float* __restrict__ W,
    const float* __restrict__ b, float* __restrict__ out)
{
    extern __shared__ __align__(16) unsigned char dynsm[];
    uint2* smB = reinterpret_cast<uint2*>(dynsm);               // B fragments
    float* uni = reinterpret_cast<float*>(dynsm + SM_UNION_OFF);
    __shared__ int isLast;

    int tid = threadIdx.x, lane = tid & 31, w = tid >> 5;
    int gy = blockIdx.y, tile = blockIdx.x;

    // ---- 1. raw Wb[r][0..8] into union (coalesced loads) ----
#pragma unroll
    for (int q = 0; q < 4; q++) {
        int r = tid * 4 + q;
        size_t gr = (size_t)gy * 512 + r;
        float4 w0 = reinterpret_cast<const float4*>(W + gr * 8)[0];
        float4 w1 = reinterpret_cast<const float4*>(W + gr * 8)[1];
        float* row = uni + r * 9;
        row[0] = w0.x; row[1] = w0.y; row[2] = w0.z; row[3] = w0.w;
        row[4] = w1.x; row[5] = w1.y; row[6] = w1.z; row[7] = w1.w;
        row[8] = b[gr];
    }
    __syncthreads();

    // ---- 2. build B fragments: smB[kt*64 + nt*32 + l] ----
    // = { tf32(Wb[8kt + l%4][n]), tf32(Wb[8kt + l%4 + 4][n]) }, n = nt*8 + l/4
#pragma unroll
    for (int idx = tid; idx < 4096; idx += 128) {
        int kt = idx >> 6, rem = idx & 63;
        int l = rem & 31;
        int n = ((rem >> 5) << 3) + (l >> 2);
        int k0 = kt * 8 + (l & 3);
        float v0 = (n < 9) ? uni[k0 * 9 + n] : 0.f;
        float v1 = (n < 9) ? uni[(k0 + 4) * 9 + n] : 0.f;
        smB[idx] = make_uint2(tf32r(v0), tf32r(v1));
    }
    __syncthreads();

    // ---- 3. memberships into union (overwrites raw Wb): [s][33] padded ----
    {
        int n = tile * 128 + tid;
        float* row = uni + tid * 33;
#pragma unroll
        for (int m = 0; m < 8; m++) {
            float xv = x[n * 8 + m];
            float e[4], sum = 0.f;
#pragma unroll
            for (int j = 0; j < 4; j++) {
                float d = xv - center[m * 4 + j];
                float sg = sigma[m * 4 + j];
                e[j] = __expf(-0.5f * d * d * sg * sg);
                sum += e[j];
            }
            float inv = 1.0f / sum;
#pragma unroll
            for (int j = 0; j < 4; j++) row[m * 4 + j] = e[j] * inv;
        }
    }
    __syncthreads();

    // ---- 4. per-thread fragment-row membership state ----
    // thread owns sample rows: w*32 + l/4 + {0,8,16,24}; rule digit j7 = l&3
    int srow = lane >> 2, j7 = lane & 3;
    const float* rs[4];
#pragma unroll
    for (int i = 0; i < 4; i++) rs[i] = uni + (w * 32 + srow + 8 * i) * 33;

    int j0 = (gy >> 5) & 3, j1 = (gy >> 3) & 3, j2 = (gy >> 1) & 3;
    float P0[4], m6r[4][4];
#pragma unroll
    for (int i = 0; i < 4; i++) {
        P0[i] = rs[i][j0] * rs[i][4 + j1] * rs[i][8 + j2] * rs[i][28 + j7];
#pragma unroll
        for (int j = 0; j < 4; j++) m6r[i][j] = rs[i][24 + j];
    }

    float d00[4] = {0,0,0,0}, d01[4] = {0,0,0,0};   // m-tile0, n-tile0/1
    float d10[4] = {0,0,0,0}, d11[4] = {0,0,0,0};   // m-tile1

    // ---- 5. mainloop: 64 k-tiles of 8 rules ----
#pragma unroll 1
    for (int t3 = 0; t3 < 2; t3++) {
        int j3 = ((gy & 1) << 1) | t3;
        float b3[4];
#pragma unroll
        for (int i = 0; i < 4; i++) b3[i] = P0[i] * rs[i][12 + j3];
#pragma unroll 1
        for (int t4 = 0; t4 < 4; t4++) {
            float b4[4];
#pragma unroll
            for (int i = 0; i < 4; i++) b4[i] = b3[i] * rs[i][16 + t4];
            const uint2* Bbase = smB + (t3 * 32 + t4 * 8) * 64 + lane;
#pragma unroll
            for (int t5 = 0; t5 < 4; t5++) {
                float b5[4];
#pragma unroll
                for (int i = 0; i < 4; i++) b5[i] = b4[i] * rs[i][20 + t5];
#pragma unroll
                for (int t6 = 0; t6 < 2; t6++) {
                    // fg elements: cols lo (j6 = 2*t6), hi (j6 = 2*t6+1)
                    uint32_t aLo[4], aHi[4];
#pragma unroll
                    for (int i = 0; i < 4; i++) {
                        aLo[i] = tf32r(b5[i] * m6r[i][t6 * 2]);
                        aHi[i] = tf32r(b5[i] * m6r[i][t6 * 2 + 1]);
                    }
                    const uint2* Bt = Bbase + (t5 * 2 + t6) * 64;
                    uint2 bf0 = Bt[0];       // n-tile 0
                    uint2 bf1 = Bt[32];      // n-tile 1
                    // m-tile0: rows srow, srow+8 -> samples idx 0, 1
                    mma8(d00, aLo[0], aLo[1], aHi[0], aHi[1], bf0.x, bf0.y);
                    mma8(d01, aLo[0], aLo[1], aHi[0], aHi[1], bf1.x, bf1.y);
                    // m-tile1: rows +16, +24 -> samples idx 2, 3
                    mma8(d10, aLo[2], aLo[3], aHi[2], aHi[3], bf0.x, bf0.y);
                    mma8(d11, aLo[2], aLo[3], aHi[2], aHi[3], bf1.x, bf1.y);
                }
            }
        }
    }

    // ---- 6. write partials: g_part[(gy*9+k)*NSAMP + n] ----
    {
        int k0 = j7 * 2;
        int n0 = tile * 128 + w * 32 + srow;
        float* gp = g_part + (size_t)gy * 9 * NSAMP;
        // m-tile0 (rows n0, n0+8), n-tile0 cols k0, k0+1
        gp[(k0 + 0) * NSAMP + n0]      = d00[0];
        gp[(k0 + 1) * NSAMP + n0]      = d00[1];
        gp[(k0 + 0) * NSAMP + n0 + 8]  = d00[2];
        gp[(k0 + 1) * NSAMP + n0 + 8]  = d00[3];
        // m-tile1 (rows n0+16, n0+24)
        gp[(k0 + 0) * NSAMP + n0 + 16] = d10[0];
        gp[(k0 + 1) * NSAMP + n0 + 16] = d10[1];
        gp[(k0 + 0) * NSAMP + n0 + 24] = d10[2];
        gp[(k0 + 1) * NSAMP + n0 + 24] = d10[3];
        if (j7 == 0) {   // n-tile1 col 8 (bias)
            gp[8 * NSAMP + n0]      = d01[0];
            gp[8 * NSAMP + n0 + 8]  = d01[2];
            gp[8 * NSAMP + n0 + 16] = d11[0];
            gp[8 * NSAMP + n0 + 24] = d11[2];
        }
    }

    // ---- 7. fused finalize: last CTA of this tile ----
    __threadfence();
    __syncthreads();
    if (tid == 0) {
        int c = atomicAdd(&g_cnt[tile], 1);
        isLast = (c == NGROUP - 1) ? 1 : 0;
    }
    __syncthreads();
    if (isLast) {
        __threadfence();
        float* sA = uni;  // reuse union: [s][k] 128*9
#pragma unroll 1
        for (int item = tid; item < 9 * 128; item += 128) {
            int k = item >> 7, s = item & 127;
            const float* p = g_part + k * NSAMP + tile * 128 + s;
            float a0 = 0.f, a1 = 0.f, a2 = 0.f, a3 = 0.f;
#pragma unroll 4
            for (int g = 0; g < NGROUP; g += 4) {
                a0 += p[(g + 0) * 9 * NSAMP];
                a1 += p[(g + 1) * 9 * NSAMP];
                a2 += p[(g + 2) * 9 * NSAMP];
                a3 += p[(g + 3) * 9 * NSAMP];
            }
            sA[s * 9 + k] = (a0 + a1) + (a2 + a3);
        }
        __syncthreads();
        {
            int n = tile * 128 + tid;
            float o = sA[tid * 9 + 8];
#pragma unroll
            for (int m = 0; m < 8; m++) o = fmaf(x[n * 8 + m], sA[tid * 9 + m], o);
            out[n] = o;
        }
        if (tid == 0) g_cnt[tile] = 0;  // reset for next graph replay
    }
}

extern "C" void kernel_launch(void* const* d_in, const int* in_sizes, int n_in,
                              void* d_out, int out_size) {
    const float* x      = (const float*)d_in[0];
    const float* center = (const float*)d_in[1];
    const float* sigma  = (const float*)d_in[2];
    const float* W      = (const float*)d_in[3];
    const float* b      = (const float*)d_in[4];
    float* out = (float*)d_out;

    cudaFuncSetAttribute(tsk_kernel, cudaFuncAttributeMaxDynamicSharedMemorySize,
                         SMEM_TOTAL);
    dim3 grid(TILES, NGROUP);
    tsk_kernel<<<grid, 128, SMEM_TOTAL>>>(x, center, sigma, W, b, out);
}

// round 11
// speedup vs baseline: 1.7007x; 1.6386x over previous
#include <cuda_runtime.h>
#include <cstdint>

// TSK fuzzy system via mma.sync tf32 tensor ops (baseline sm_80+ ISA).
// out[n] = sum_r fg_bar[n,r]*(x[n]·W[r]+b[r]); fg_bar separable-normalized:
// fg_bar[n,r] = prod_m mgn[n,m,digit_m(r)], mgn = mg/sum_j mg.
// Per CTA (tile of 128 samples, group of 512 rules):
//   D[128x16] = FG[128x512] @ Wb^T,  Wb[r] = [W[r][0..7], b[r], 0,...]
// FG fragments generated in registers; Wb^T staged in smem in m16n8k8 B layout.
// Finalization split into two small parallel kernels (the fused last-CTA
// finisher was a ~40us serialized tail).

#define NSAMP 1024
#define NGROUP 128   // grid.y: rule groups of 512
#define TILES 8      // grid.x: sample tiles of 128

#define SM_UNION_OFF 32768
#define SMEM_TOTAL (32768 + 18432)

__device__ float g_part[NGROUP * 9 * NSAMP];  // [g][k][n]
__device__ float g_A[9 * NSAMP];              // [k][n] reduced

__device__ __forceinline__ uint32_t tf32r(float f) {
    uint32_t r; asm("cvt.rna.tf32.f32 %0, %1;" : "=r"(r) : "f"(f)); return r;
}
__device__ __forceinline__ void mma8(float* d, uint32_t a0, uint32_t a1,
                                     uint32_t a2, uint32_t a3,
                                     uint32_t b0, uint32_t b1) {
    asm volatile(
        "mma.sync.aligned.m16n8k8.row.col.f32.tf32.tf32.f32 "
        "{%0,%1,%2,%3}, {%4,%5,%6,%7}, {%8,%9}, {%0,%1,%2,%3};"
        : "+f"(d[0]), "+f"(d[1]), "+f"(d[2]), "+f"(d[3])
        : "r"(a0), "r"(a1), "r"(a2), "r"(a3), "r"(b0), "r"(b1));
}

__global__ __launch_bounds__(128) void tsk_kernel(
    const float* __restrict__ x, const float* __restrict__ center,
    const float* __restrict__ sigma, const float* __restrict__ W,
    const float* __restrict__ b)
{
    extern __shared__ __align__(16) unsigned char dynsm[];
    uint2* smB = reinterpret_cast<uint2*>(dynsm);               // B fragments
    float* uni = reinterpret_cast<float*>(dynsm + SM_UNION_OFF);

    int tid = threadIdx.x, lane = tid & 31, w = tid >> 5;
    int gy = blockIdx.y, tile = blockIdx.x;

    // ---- 1. raw Wb[r][0..8] into union (coalesced loads) ----
#pragma unroll
    for (int q = 0; q < 4; q++) {
        int r = tid * 4 + q;
        size_t gr = (size_t)gy * 512 + r;
        float4 w0 = reinterpret_cast<const float4*>(W + gr * 8)[0];
        float4 w1 = reinterpret_cast<const float4*>(W + gr * 8)[1];
        float* row = uni + r * 9;
        row[0] = w0.x; row[1] = w0.y; row[2] = w0.z; row[3] = w0.w;
        row[4] = w1.x; row[5] = w1.y; row[6] = w1.z; row[7] = w1.w;
        row[8] = b[gr];
    }
    __syncthreads();

    // ---- 2. build B fragments: smB[kt*64 + nt*32 + l] ----
    // = { tf32(Wb[8kt + l%4][n]), tf32(Wb[8kt + l%4 + 4][n]) }, n = nt*8 + l/4
#pragma unroll
    for (int idx = tid; idx < 4096; idx += 128) {
        int kt = idx >> 6, rem = idx & 63;
        int l = rem & 31;
        int n = ((rem >> 5) << 3) + (l >> 2);
        int k0 = kt * 8 + (l & 3);
        float v0 = (n < 9) ? uni[k0 * 9 + n] : 0.f;
        float v1 = (n < 9) ? uni[(k0 + 4) * 9 + n] : 0.f;
        smB[idx] = make_uint2(tf32r(v0), tf32r(v1));
    }
    __syncthreads();

    // ---- 3. memberships into union (overwrites raw Wb): [s][33] padded ----
    {
        int n = tile * 128 + tid;
        float* row = uni + tid * 33;
#pragma unroll
        for (int m = 0; m < 8; m++) {
            float xv = x[n * 8 + m];
            float e[4], sum = 0.f;
#pragma unroll
            for (int j = 0; j < 4; j++) {
                float d = xv - center[m * 4 + j];
                float sg = sigma[m * 4 + j];
                e[j] = __expf(-0.5f * d * d * sg * sg);
                sum += e[j];
            }
            float inv = 1.0f / sum;
#pragma unroll
            for (int j = 0; j < 4; j++) row[m * 4 + j] = e[j] * inv;
        }
    }
    __syncthreads();

    // ---- 4. per-thread fragment-row membership state ----
    // thread owns sample rows: w*32 + l/4 + {0,8,16,24}; rule digit j7 = l&3
    int srow = lane >> 2, j7 = lane & 3;
    const float* rs[4];
#pragma unroll
    for (int i = 0; i < 4; i++) rs[i] = uni + (w * 32 + srow + 8 * i) * 33;

    int j0 = (gy >> 5) & 3, j1 = (gy >> 3) & 3, j2 = (gy >> 1) & 3;
    float P0[4], m6r[4][4];
#pragma unroll
    for (int i = 0; i < 4; i++) {
        P0[i] = rs[i][j0] * rs[i][4 + j1] * rs[i][8 + j2] * rs[i][28 + j7];
#pragma unroll
        for (int j = 0; j < 4; j++) m6r[i][j] = rs[i][24 + j];
    }

    float d00[4] = {0,0,0,0}, d01[4] = {0,0,0,0};   // m-tile0, n-tile0/1
    float d10[4] = {0,0,0,0}, d11[4] = {0,0,0,0};   // m-tile1

    // ---- 5. mainloop: 64 k-tiles of 8 rules ----
#pragma unroll 1
    for (int t3 = 0; t3 < 2; t3++) {
        int j3 = ((gy & 1) << 1) | t3;
        float b3[4];
#pragma unroll
        for (int i = 0; i < 4; i++) b3[i] = P0[i] * rs[i][12 + j3];
#pragma unroll 1
        for (int t4 = 0; t4 < 4; t4++) {
            float b4[4];
#pragma unroll
            for (int i = 0; i < 4; i++) b4[i] = b3[i] * rs[i][16 + t4];
            const uint2* Bbase = smB + (t3 * 32 + t4 * 8) * 64 + lane;
#pragma unroll
            for (int t5 = 0; t5 < 4; t5++) {
                float b5[4];
#pragma unroll
                for (int i = 0; i < 4; i++) b5[i] = b4[i] * rs[i][20 + t5];
#pragma unroll
                for (int t6 = 0; t6 < 2; t6++) {
                    uint32_t aLo[4], aHi[4];
#pragma unroll
                    for (int i = 0; i < 4; i++) {
                        aLo[i] = tf32r(b5[i] * m6r[i][t6 * 2]);
                        aHi[i] = tf32r(b5[i] * m6r[i][t6 * 2 + 1]);
                    }
                    const uint2* Bt = Bbase + (t5 * 2 + t6) * 64;
                    uint2 bf0 = Bt[0];       // n-tile 0
                    uint2 bf1 = Bt[32];      // n-tile 1
                    mma8(d00, aLo[0], aLo[1], aHi[0], aHi[1], bf0.x, bf0.y);
                    mma8(d01, aLo[0], aLo[1], aHi[0], aHi[1], bf1.x, bf1.y);
                    mma8(d10, aLo[2], aLo[3], aHi[2], aHi[3], bf0.x, bf0.y);
                    mma8(d11, aLo[2], aLo[3], aHi[2], aHi[3], bf1.x, bf1.y);
                }
            }
        }
    }

    // ---- 6. write partials: g_part[(gy*9+k)*NSAMP + n] ----
    {
        int k0 = j7 * 2;
        int n0 = tile * 128 + w * 32 + srow;
        float* gp = g_part + (size_t)gy * 9 * NSAMP;
        gp[(k0 + 0) * NSAMP + n0]      = d00[0];
        gp[(k0 + 1) * NSAMP + n0]      = d00[1];
        gp[(k0 + 0) * NSAMP + n0 + 8]  = d00[2];
        gp[(k0 + 1) * NSAMP + n0 + 8]  = d00[3];
        gp[(k0 + 0) * NSAMP + n0 + 16] = d10[0];
        gp[(k0 + 1) * NSAMP + n0 + 16] = d10[1];
        gp[(k0 + 0) * NSAMP + n0 + 24] = d10[2];
        gp[(k0 + 1) * NSAMP + n0 + 24] = d10[3];
        if (j7 == 0) {   // bias column
            gp[8 * NSAMP + n0]      = d01[0];
            gp[8 * NSAMP + n0 + 8]  = d01[2];
            gp[8 * NSAMP + n0 + 16] = d11[0];
            gp[8 * NSAMP + n0 + 24] = d11[2];
        }
    }
}

// ---- reduce: A[k][n] = sum_g g_part[g][k][n]; one thread per (k,n) ----
__global__ __launch_bounds__(256) void reduce_kernel() {
    int id = blockIdx.x * 256 + threadIdx.x;   // id = k*NSAMP + n, < 9*NSAMP
    const float* p = g_part + id;
    float a0 = 0.f, a1 = 0.f, a2 = 0.f, a3 = 0.f;
    float a4 = 0.f, a5 = 0.f, a6 = 0.f, a7 = 0.f;
    const int stride = 9 * NSAMP;
#pragma unroll 2
    for (int g = 0; g < NGROUP; g += 8) {
        a0 += p[(g + 0) * stride];
        a1 += p[(g + 1) * stride];
        a2 += p[(g + 2) * stride];
        a3 += p[(g + 3) * stride];
        a4 += p[(g + 4) * stride];
        a5 += p[(g + 5) * stride];
        a6 += p[(g + 6) * stride];
        a7 += p[(g + 7) * stride];
    }
    g_A[id] = ((a0 + a1) + (a2 + a3)) + ((a4 + a5) + (a6 + a7));
}

// ---- out[n] = x[n]·A[:,n] + c[n] ----
__global__ __launch_bounds__(256) void out_kernel(const float* __restrict__ x,
                                                  float* __restrict__ out) {
    int n = blockIdx.x * 256 + threadIdx.x;
    float o = g_A[8 * NSAMP + n];
#pragma unroll
    for (int m = 0; m < 8; m++) o = fmaf(x[n * 8 + m], g_A[m * NSAMP + n], o);
    out[n] = o;
}

extern "C" void kernel_launch(void* const* d_in, const int* in_sizes, int n_in,
                              void* d_out, int out_size) {
    const float* x      = (const float*)d_in[0];
    const float* center = (const float*)d_in[1];
    const float* sigma  = (const float*)d_in[2];
    const float* W      = (const float*)d_in[3];
    const float* b      = (const float*)d_in[4];
    float* out = (float*)d_out;

    cudaFuncSetAttribute(tsk_kernel, cudaFuncAttributeMaxDynamicSharedMemorySize,
                         SMEM_TOTAL);
    dim3 grid(TILES, NGROUP);
    tsk_kernel<<<grid, 128, SMEM_TOTAL>>>(x, center, sigma, W, b);
    reduce_kernel<<<(9 * NSAMP) / 256, 256>>>();
    out_kernel<<<NSAMP / 256, 256>>>(x, out);
}